// round 16
// baseline (speedup 1.0000x reference)
#include <cuda_runtime.h>
#include <cuda_bf16.h>

// EmbeddingSumConcat: out[b, f*E+e] = sum_{l < lengths[b,f]} tables[f, ids[b,f,l], e]
// B=4096, F=32, V=100000, L=20, E=64. ids/lengths int32 (JAX x64 disabled),
// tables/out fp32.
//
// FINAL (R13 config, confirmed optimum of the depth/occupancy frontier):
//  - LDG.256 gathers (ld.global.nc.L2::evict_last.v8.b32): one warp-instr =
//    one full 256B table row; minimal instruction overhead, max bytes per
//    scoreboard entry. evict_last protects the only reusable stream in L2.
//  - f-major cell order: co-resident CTAs share one 25.6MB table column ->
//    L2 dedups repeated rows; DRAM volume sits at the compulsory floor.
//  - ids staged in smem (cooperative 5x int4 per cell) to free registers for
//    in-flight load batches; __launch_bounds__(128,8) = 32 warps/SM x 64 regs,
//    the measured peak (24w:57.9 / 32w:53.7 / 36w:54.0 / 48w:56.0 / 64w:72.2).
//  - __stcs streaming stores keep the write-once output from evicting table
//    rows out of L2.

#define EB_B 4096
#define EB_F 32
#define EB_V 100000
#define EB_L 20
#define EB_E 64
#define EB_V8 (EB_E / 8)     // 8 lanes of 8 floats (32B) per row
#define EB_CPB 16            // cells per 128-thread block

__global__ __launch_bounds__(128, 8) void embbag_kernel(
    const int*   __restrict__ ids,      // int32 [B, F, L]
    const int*   __restrict__ lengths,  // int32 [B, F]
    const float* __restrict__ tables,   // fp32  [F, V, E]
    float*       __restrict__ out)      // fp32  [B, F, E]
{
    __shared__ __align__(16) int s_ids[EB_CPB][EB_L];   // 1280 B

    int t    = threadIdx.x;
    int tid  = blockIdx.x * 128 + t;                // 0 .. B*F*8-1
    int v    = tid & (EB_V8 - 1);                   // 32B lane in row (0..7)
    int cl   = t >> 3;                              // cell within block (0..15)
    int cell = tid >> 3;                            // f-major: cell = f*B + b
    int b    = cell & (EB_B - 1);                   // B = 4096 = 2^12
    int f    = cell >> 12;

    size_t bf = (size_t)b * EB_F + f;
    int n = lengths[bf];                            // 0..20
    const float* base = tables + (size_t)f * EB_V * EB_E + v * 8;

    // Cooperative id load: 80B per cell = 5 int4; lanes 0-4 of each cell each
    // fetch one int4 into smem. Loaders and readers share a warp
    // (4 cells per warp), so __syncwarp suffices.
    if (v < 5) {
        const int4* idp4 = (const int4*)(ids + bf * EB_L);
        ((int4*)s_ids[cl])[v] = __ldg(&idp4[v]);
    }
    __syncwarp();

    float a0 = 0.f, a1 = 0.f, a2 = 0.f, a3 = 0.f;
    float a4 = 0.f, a5 = 0.f, a6 = 0.f, a7 = 0.f;
#pragma unroll
    for (int l = 0; l < EB_L; l++) {
        if (l < n) {
            int id = s_ids[cl][l];                  // LDS broadcast, conflict-free
            const float* p = base + (size_t)id * EB_E;
            unsigned u0, u1, u2, u3, u4, u5, u6, u7;
            asm volatile(
                "ld.global.nc.L2::evict_last.v8.b32 "
                "{%0,%1,%2,%3,%4,%5,%6,%7}, [%8];"
                : "=r"(u0), "=r"(u1), "=r"(u2), "=r"(u3),
                  "=r"(u4), "=r"(u5), "=r"(u6), "=r"(u7)
                : "l"(p));
            a0 += __uint_as_float(u0); a1 += __uint_as_float(u1);
            a2 += __uint_as_float(u2); a3 += __uint_as_float(u3);
            a4 += __uint_as_float(u4); a5 += __uint_as_float(u5);
            a6 += __uint_as_float(u6); a7 += __uint_as_float(u7);
        }
    }

    // Streaming stores: written once, never re-read.
    float4* op = (float4*)(out + bf * EB_E + v * 8);
    __stcs(&op[0], make_float4(a0, a1, a2, a3));
    __stcs(&op[1], make_float4(a4, a5, a6, a7));
}

extern "C" void kernel_launch(void* const* d_in, const int* in_sizes, int n_in,
                              void* d_out, int out_size) {
    const int*   ids     = (const int*)d_in[0];     // int32 [B,F,L]
    const int*   lengths = (const int*)d_in[1];     // int32 [B,F]
    const float* tables  = (const float*)d_in[2];   // fp32  [F,V,E]
    float*       out     = (float*)d_out;           // fp32  [B,F*E]

    int total = EB_B * EB_F * EB_V8;                // 1,048,576 threads
    embbag_kernel<<<total / 128, 128>>>(ids, lengths, tables, out);
}

// round 17
// speedup vs baseline: 1.0160x; 1.0160x over previous
#include <cuda_runtime.h>
#include <cuda_bf16.h>

// EmbeddingSumConcat: out[b, f*E+e] = sum_{l < lengths[b,f]} tables[f, ids[b,f,l], e]
// B=4096, F=32, V=100000, L=20, E=64. ids/lengths int32 (JAX x64 disabled),
// tables/out fp32.
//
// FINAL — converged champion (53.7-54.8us across re-benches, noise band).
//  - LDG.256 gathers (ld.global.nc.L2::evict_last.v8.b32): one warp-instr =
//    one full 256B table row; minimal instruction overhead, max bytes per
//    scoreboard entry. evict_last protects the only reusable stream in L2.
//  - f-major cell order: co-resident CTAs share one 25.6MB table column ->
//    L2 dedups repeated rows; DRAM volume sits at the compulsory floor
//    (~315MB measured).
//  - ids staged in smem (cooperative 5x int4 per cell) frees registers for
//    in-flight load batches; __launch_bounds__(128,8) = 32 warps/SM x 64 regs,
//    the measured frontier peak (24w:57.9 / 32w:53.7 / 36w:54.0 / 48w:56.0 /
//    64w:72.2).
//  - __stcs streaming stores keep the write-once output from evicting table
//    rows out of L2.
// Measured ceiling: DRAM ~74.5% of spec on random 256B rows; supply-side
// levers (depth, occupancy, cp.async, load width) all measured worse.

#define EB_B 4096
#define EB_F 32
#define EB_V 100000
#define EB_L 20
#define EB_E 64
#define EB_V8 (EB_E / 8)     // 8 lanes of 8 floats (32B) per row
#define EB_CPB 16            // cells per 128-thread block

__global__ __launch_bounds__(128, 8) void embbag_kernel(
    const int*   __restrict__ ids,      // int32 [B, F, L]
    const int*   __restrict__ lengths,  // int32 [B, F]
    const float* __restrict__ tables,   // fp32  [F, V, E]
    float*       __restrict__ out)      // fp32  [B, F, E]
{
    __shared__ __align__(16) int s_ids[EB_CPB][EB_L];   // 1280 B

    int t    = threadIdx.x;
    int tid  = blockIdx.x * 128 + t;                // 0 .. B*F*8-1
    int v    = tid & (EB_V8 - 1);                   // 32B lane in row (0..7)
    int cl   = t >> 3;                              // cell within block (0..15)
    int cell = tid >> 3;                            // f-major: cell = f*B + b
    int b    = cell & (EB_B - 1);                   // B = 4096 = 2^12
    int f    = cell >> 12;

    size_t bf = (size_t)b * EB_F + f;
    int n = lengths[bf];                            // 0..20
    const float* base = tables + (size_t)f * EB_V * EB_E + v * 8;

    // Cooperative id load: 80B per cell = 5 int4; lanes 0-4 of each cell each
    // fetch one int4 into smem. Loaders and readers share a warp
    // (4 cells per warp), so __syncwarp suffices.
    if (v < 5) {
        const int4* idp4 = (const int4*)(ids + bf * EB_L);
        ((int4*)s_ids[cl])[v] = __ldg(&idp4[v]);
    }
    __syncwarp();

    float a0 = 0.f, a1 = 0.f, a2 = 0.f, a3 = 0.f;
    float a4 = 0.f, a5 = 0.f, a6 = 0.f, a7 = 0.f;
#pragma unroll
    for (int l = 0; l < EB_L; l++) {
        if (l < n) {
            int id = s_ids[cl][l];                  // LDS broadcast, conflict-free
            const float* p = base + (size_t)id * EB_E;
            unsigned u0, u1, u2, u3, u4, u5, u6, u7;
            asm volatile(
                "ld.global.nc.L2::evict_last.v8.b32 "
                "{%0,%1,%2,%3,%4,%5,%6,%7}, [%8];"
                : "=r"(u0), "=r"(u1), "=r"(u2), "=r"(u3),
                  "=r"(u4), "=r"(u5), "=r"(u6), "=r"(u7)
                : "l"(p));
            a0 += __uint_as_float(u0); a1 += __uint_as_float(u1);
            a2 += __uint_as_float(u2); a3 += __uint_as_float(u3);
            a4 += __uint_as_float(u4); a5 += __uint_as_float(u5);
            a6 += __uint_as_float(u6); a7 += __uint_as_float(u7);
        }
    }

    // Streaming stores: written once, never re-read.
    float4* op = (float4*)(out + bf * EB_E + v * 8);
    __stcs(&op[0], make_float4(a0, a1, a2, a3));
    __stcs(&op[1], make_float4(a4, a5, a6, a7));
}

extern "C" void kernel_launch(void* const* d_in, const int* in_sizes, int n_in,
                              void* d_out, int out_size) {
    const int*   ids     = (const int*)d_in[0];     // int32 [B,F,L]
    const int*   lengths = (const int*)d_in[1];     // int32 [B,F]
    const float* tables  = (const float*)d_in[2];   // fp32  [F,V,E]
    float*       out     = (float*)d_out;           // fp32  [B,F*E]

    int total = EB_B * EB_F * EB_V8;                // 1,048,576 threads
    embbag_kernel<<<total / 128, 128>>>(ids, lengths, tables, out);
}